// round 7
// baseline (speedup 1.0000x reference)
#include <cuda_runtime.h>
#include <cuda_bf16.h>

#define TOK    9216
#define NTOT   288
#define LAT    256
#define DIN    512
#define NE     8
#define HID    128
#define OUTD   16384
#define BMOFF  75497472
#define AUXOFF 150994944

typedef unsigned long long ull;

// ---------------- device scratch (no allocation allowed) ----------------
__device__ float g_Hg[2 * TOK * HID];        // gate-scaled silu hidden, per slot
__device__ int   g_list[2][NE][TOK];         // token lists per (slot, expert)
__device__ int   g_cnt[2][NE];
__device__ float g_tokG[2 * TOK];            // gate per (slot, token)
__device__ float g_psum[96][NE];             // per-(b,s) softmax prob partials
__device__ float g_lsum[96][NE];             // per-(b,s) load partials

__device__ __forceinline__ void fma2(ull& d, ull a, ull b) {
    asm("fma.rn.f32x2 %0, %1, %2, %0;" : "+l"(d) : "l"(a), "l"(b));
}
__device__ __forceinline__ ull pack2(float x) {
    ull r; asm("mov.b64 %0, {%1, %1};" : "=l"(r) : "f"(x)); return r;
}

// ---------------- K0: reset counters (device globals persist across graph replays)
__global__ void k_zero() {
    if (threadIdx.x < 16) ((int*)g_cnt)[threadIdx.x] = 0;
}

// ---------------- K1: routing. 96 blocks = one per (b, segment); 4 warps x 24 tokens.
__global__ void k_route(const float* __restrict__ z, const float* __restrict__ emb,
                        const float* __restrict__ Wr, const float* __restrict__ br) {
    int blk = blockIdx.x;            // b*3 + s
    int b = blk / 3, s = blk - b * 3;
    int warp = threadIdx.x >> 5, lane = threadIdx.x & 31;
    float accP = 0.f, accL = 0.f;    // lanes 0..7 accumulate for e == lane

    for (int it = 0; it < 24; it++) {
        int tt = warp * 24 + it;
        int n  = s * 96 + tt;
        int t  = b * NTOT + n;
        float lg[8];
#pragma unroll
        for (int e = 0; e < 8; e++) lg[e] = 0.f;
        const float* zr = z + (size_t)t * LAT;
        const float* er = emb + (size_t)n * LAT;
        for (int i = lane; i < DIN; i += 32) {
            float xv = (i < LAT) ? zr[i] : er[i - LAT];
            const float4 w0 = *(const float4*)(Wr + i * 8);
            const float4 w1 = *(const float4*)(Wr + i * 8 + 4);
            lg[0] += xv * w0.x; lg[1] += xv * w0.y; lg[2] += xv * w0.z; lg[3] += xv * w0.w;
            lg[4] += xv * w1.x; lg[5] += xv * w1.y; lg[6] += xv * w1.z; lg[7] += xv * w1.w;
        }
#pragma unroll
        for (int off = 16; off > 0; off >>= 1) {
#pragma unroll
            for (int e = 0; e < 8; e++) lg[e] += __shfl_xor_sync(0xffffffffu, lg[e], off);
        }
#pragma unroll
        for (int e = 0; e < 8; e++) lg[e] = (lg[e] + br[e]) * (1.0f / 1.5f);

        // top-2 (lowest index wins ties, matching jax top_k)
        int e0 = 0; float v0 = lg[0];
#pragma unroll
        for (int e = 1; e < 8; e++) if (lg[e] > v0) { v0 = lg[e]; e0 = e; }
        int e1 = -1; float v1 = -3.4e38f;
#pragma unroll
        for (int e = 0; e < 8; e++) if (e != e0 && lg[e] > v1) { v1 = lg[e]; e1 = e; }
        float ex = __expf(v1 - v0);
        float g0 = 1.f / (1.f + ex);
        float g1 = ex * g0;

        float den = 0.f, pr[8];
#pragma unroll
        for (int e = 0; e < 8; e++) { pr[e] = __expf(lg[e] - v0); den += pr[e]; }
        float rden = 1.f / den;
        if (lane < 8) {
            accP += pr[lane] * rden;
            accL += (lane == e0 ? g0 : 0.f) + (lane == e1 ? g1 : 0.f);
        }
        if (lane == 0) {
            g_tokG[t]       = g0;
            g_tokG[TOK + t] = g1;
            int p0 = atomicAdd(&g_cnt[0][e0], 1); g_list[0][e0][p0] = t;
            int p1 = atomicAdd(&g_cnt[1][e1], 1); g_list[1][e1][p1] = t;
        }
    }
    __shared__ float sP[4][8], sL[4][8];
    if (lane < 8) { sP[warp][lane] = accP; sL[warp][lane] = accL; }
    __syncthreads();
    if (threadIdx.x < 8) {
        float p = 0.f, l = 0.f;
        for (int w = 0; w < 4; w++) { p += sP[w][threadIdx.x]; l += sL[w][threadIdx.x]; }
        g_psum[blk][threadIdx.x] = p;
        g_lsum[blk][threadIdx.x] = l;
    }
}

// ---------------- K2: hidden GEMM per (slot, expert): [cnt,512] @ [512,128], silu, *gate
__global__ void __launch_bounds__(256) k_hidden(const float* __restrict__ z,
                                                const float* __restrict__ emb,
                                                const float* __restrict__ W1,
                                                const float* __restrict__ b1) {
    int slot = blockIdx.z, e = blockIdx.y;
    int cnt = g_cnt[slot][e];
    int m0 = blockIdx.x * 64;
    if (m0 >= cnt) return;
    int rows = min(64, cnt - m0);

    __shared__ __align__(16) float Xs[16][64];
    __shared__ __align__(16) float Ws[16][128];
    __shared__ int   stok[64];
    __shared__ float sg[64];

    int tid = threadIdx.x;
    if (tid < 64) {
        int t = (tid < rows) ? g_list[slot][e][m0 + tid] : -1;
        stok[tid] = t;
        sg[tid]   = (t >= 0) ? g_tokG[slot * TOK + t] : 0.f;
    }
    __syncthreads();

    int tx = tid & 15, ty = tid >> 4;
    int j0 = tx * 8, mr = ty * 4;
    float acc[4][8];
#pragma unroll
    for (int a = 0; a < 4; a++)
#pragma unroll
        for (int j = 0; j < 8; j++) acc[a][j] = 0.f;

    const float* W1e = W1 + (size_t)e * DIN * HID;
    int lm = tid >> 2, lq = (tid & 3) * 4;       // X-load mapping
    int lk = tid >> 4, ln = (tid & 15) * 8;      // W-load mapping

    for (int k0 = 0; k0 < DIN; k0 += 16) {
        float4 v = make_float4(0.f, 0.f, 0.f, 0.f);
        int t = stok[lm];
        if (t >= 0) {
            int kk = k0 + lq;
            if (kk < LAT) v = *(const float4*)(z + (size_t)t * LAT + kk);
            else          v = *(const float4*)(emb + (size_t)(t % NTOT) * LAT + (kk - LAT));
        }
        const float* src = W1e + (size_t)(k0 + lk) * HID + ln;
        float4 w0 = *(const float4*)src;
        float4 w1 = *(const float4*)(src + 4);

        __syncthreads();    // previous compute done before overwrite
        Xs[lq + 0][lm] = v.x; Xs[lq + 1][lm] = v.y; Xs[lq + 2][lm] = v.z; Xs[lq + 3][lm] = v.w;
        *(float4*)&Ws[lk][ln]     = w0;
        *(float4*)&Ws[lk][ln + 4] = w1;
        __syncthreads();

#pragma unroll
        for (int kk = 0; kk < 16; kk++) {
            float4 a  = *(const float4*)&Xs[kk][mr];
            float4 b0 = *(const float4*)&Ws[kk][j0];
            float4 b1v = *(const float4*)&Ws[kk][j0 + 4];
            float av[4] = {a.x, a.y, a.z, a.w};
            float bv[8] = {b0.x, b0.y, b0.z, b0.w, b1v.x, b1v.y, b1v.z, b1v.w};
#pragma unroll
            for (int mm = 0; mm < 4; mm++)
#pragma unroll
                for (int jj = 0; jj < 8; jj++)
                    acc[mm][jj] = fmaf(av[mm], bv[jj], acc[mm][jj]);
        }
    }

    const float* b1e = b1 + e * HID;
#pragma unroll
    for (int mm = 0; mm < 4; mm++) {
        int m = mr + mm;
        int t = stok[m];
        if (t < 0) continue;
        float g = sg[m];
        float o[8];
#pragma unroll
        for (int jj = 0; jj < 8; jj++) {
            float c = acc[mm][jj] + b1e[j0 + jj];
            float sv = 1.f / (1.f + __expf(-c));   // silu = c * sigmoid(c)
            o[jj] = c * sv * g;
        }
        float* dst = g_Hg + ((size_t)(slot * TOK + t)) * HID + j0;
        *(float4*)dst       = make_float4(o[0], o[1], o[2], o[3]);
        *(float4*)(dst + 4) = make_float4(o[4], o[5], o[6], o[7]);
    }
}

// ---------------- K3: output GEMM per (slot, expert). Tile 64 tokens x 128 cols,
// col j -> o(j) = (j>>3)*1024 + h0 + (j&7)  (all 16 r x 8 h) so Bm rows write coalesced.
__global__ void __launch_bounds__(128) k_out(const float* __restrict__ W2,
                                             const float* __restrict__ b2,
                                             float* __restrict__ out, int slot) {
    int e = blockIdx.z;
    int cnt = g_cnt[slot][e];
    int m0 = blockIdx.x * 64;
    if (m0 >= cnt) return;
    int rows = min(64, cnt - m0);
    int h0 = blockIdx.y * 8;

    __shared__ __align__(16) float As[128 * 64];   // [k][m]; reused as C tile [m][128]
    __shared__ __align__(16) float Bs[2][8 * 128];
    __shared__ int   sbase[64];
    __shared__ float sg[64];

    int tid = threadIdx.x;
    if (tid < 64) {
        int base = -1; float g = 0.f;
        if (tid < rows) {
            int t = g_list[slot][e][m0 + tid];
            g = g_tokG[slot * TOK + t];
            int b = t / NTOT, n = t - b * NTOT;
            int s = n / 96, rem = n - s * 96, l = rem >> 2, jt = rem & 3;
            int chunk = ((b * 3 + s) * 24 + l) * 2 + (jt >> 1);
            base = chunk * OUTD + (jt & 1);        // low bit = isBm (base multiple of 16384)
        }
        sbase[tid] = base; sg[tid] = g;
    }
    // load As (K-major): 2 threads per token row
    {
        int m = tid >> 1, half = tid & 1;
        int t = (m < rows) ? g_list[slot][e][m0 + m] : -1;
        const float* src = (t >= 0) ? (g_Hg + ((size_t)(slot * TOK + t)) * HID + half * 64)
                                    : (const float*)0;
#pragma unroll
        for (int q = 0; q < 16; q++) {
            float4 v = make_float4(0.f, 0.f, 0.f, 0.f);
            if (t >= 0) v = *(const float4*)(src + q * 4);
            int k = half * 64 + q * 4;
            As[(k + 0) * 64 + m] = v.x; As[(k + 1) * 64 + m] = v.y;
            As[(k + 2) * 64 + m] = v.z; As[(k + 3) * 64 + m] = v.w;
        }
    }
    const float* W2e = W2 + (size_t)e * HID * OUTD;
    int lk = tid >> 4, lr = tid & 15;
    const float* bsrc0 = W2e + (size_t)lk * OUTD + lr * 1024 + h0;

    float4 p0 = *(const float4*)bsrc0;
    float4 p1 = *(const float4*)(bsrc0 + 4);
    {
        float* d = &Bs[0][lk * 128 + lr * 8];
        *(float4*)d = p0; *(float4*)(d + 4) = p1;
    }
    __syncthreads();

    int tx = tid & 15, ty = tid >> 4;
    int j0 = tx * 8, mr = ty * 8;
    ull acc[8][4];
#pragma unroll
    for (int a = 0; a < 8; a++)
#pragma unroll
        for (int p = 0; p < 4; p++) acc[a][p] = 0ull;

    for (int c = 0; c < 16; c++) {
        if (c < 15) {
            const float* bs = bsrc0 + (size_t)(c + 1) * 8 * OUTD;
            p0 = *(const float4*)bs;
            p1 = *(const float4*)(bs + 4);
        }
        const float* Bp = &Bs[c & 1][0];
#pragma unroll
        for (int kk = 0; kk < 8; kk++) {
            const float* ar = &As[(c * 8 + kk) * 64 + mr];
            float4 a0 = *(const float4*)ar;
            float4 a1 = *(const float4*)(ar + 4);
            ull A2[8];
            A2[0] = pack2(a0.x); A2[1] = pack2(a0.y); A2[2] = pack2(a0.z); A2[3] = pack2(a0.w);
            A2[4] = pack2(a1.x); A2[5] = pack2(a1.y); A2[6] = pack2(a1.z); A2[7] = pack2(a1.w);
            ulonglong2 b01 = *(const ulonglong2*)(Bp + kk * 128 + j0);
            ulonglong2 b23 = *(const ulonglong2*)(Bp + kk * 128 + j0 + 4);
            ull B2[4] = {b01.x, b01.y, b23.x, b23.y};
#pragma unroll
            for (int mm = 0; mm < 8; mm++)
#pragma unroll
                for (int p = 0; p < 4; p++)
                    fma2(acc[mm][p], A2[mm], B2[p]);
        }
        if (c < 15) {
            float* d = &Bs[(c + 1) & 1][lk * 128 + lr * 8];
            *(float4*)d = p0; *(float4*)(d + 4) = p1;
        }
        __syncthreads();
    }

    // stage C tile through smem so each row can use its own (A vs Bm) thread mapping
    float* Cs = As;
#pragma unroll
    for (int mm = 0; mm < 8; mm++)
#pragma unroll
        for (int p = 0; p < 4; p++)
            *(ull*)&Cs[(mr + mm) * 128 + j0 + p * 2] = acc[mm][p];
    __syncthreads();

    const float* b2e = b2 + e * OUTD;
    float bA = b2e[(tid >> 3) * 1024 + h0 + (tid & 7)];
    float bB = b2e[(tid & 15) * 1024 + h0 + (tid >> 4)];
    int jB = (tid & 15) * 8 + (tid >> 4);
    int aoffA = (tid >> 3) * 1024 + h0 + (tid & 7);
    int aoffB = h0 * 16 + tid;

#pragma unroll 4
    for (int m = 0; m < 64; m++) {
        int bs = sbase[m];
        if (bs < 0) continue;
        float g = sg[m];
        size_t addr; float v;
        if (bs & 1) {   // Bm row: contiguous 128-float write
            v = Cs[m * 128 + jB] + g * bB;
            addr = (size_t)BMOFF + (size_t)(bs & ~1) + aoffB;
        } else {        // A row: 32B-sector writes
            v = Cs[m * 128 + tid] + g * bA;
            addr = (size_t)bs + aoffA;
        }
        if (slot == 0) out[addr] = v;
        else           out[addr] += v;
    }
}

// ---------------- K4: aux loss (deterministic serial reduce of partials)
__global__ void k_aux(float* __restrict__ out) {
    if (threadIdx.x == 0 && blockIdx.x == 0) {
        double aux = 0.0;
        for (int s = 0; s < 3; s++) {
            double dot = 0.0;
            for (int e = 0; e < NE; e++) {
                double P = 0.0, L = 0.0;
                for (int b = 0; b < 32; b++) {
                    P += (double)g_psum[b * 3 + s][e];
                    L += (double)g_lsum[b * 3 + s][e];
                }
                dot += P * L;
            }
            double a = 8.0 * dot / (3072.0 * 3072.0) - 1.0;
            if (a > 0.0) aux += a;
        }
        out[AUXOFF] = (float)aux;
    }
}

extern "C" void kernel_launch(void* const* d_in, const int* in_sizes, int n_in,
                              void* d_out, int out_size) {
    const float* z   = (const float*)d_in[0];
    const float* emb = (const float*)d_in[1];
    const float* Wr  = (const float*)d_in[2];
    const float* br  = (const float*)d_in[3];
    const float* W1  = (const float*)d_in[4];
    const float* b1  = (const float*)d_in[5];
    const float* W2  = (const float*)d_in[6];
    const float* b2  = (const float*)d_in[7];
    float* out = (float*)d_out;
    (void)in_sizes; (void)n_in; (void)out_size;

    k_zero<<<1, 32>>>();
    k_route<<<96, 128>>>(z, emb, Wr, br);
    k_hidden<<<dim3(TOK / 64, NE, 2), 256>>>(z, emb, W1, b1);
    k_out<<<dim3(TOK / 64, OUTD / 128, NE), 128>>>(W2, b2, out, 0);
    k_out<<<dim3(TOK / 64, OUTD / 128, NE), 128>>>(W2, b2, out, 1);
    k_aux<<<1, 32>>>(out);
}

// round 9
// speedup vs baseline: 1.4801x; 1.4801x over previous
#include <cuda_runtime.h>
#include <cuda_bf16.h>

#define TOK    9216
#define NTOT   288
#define LAT    256
#define DIN    512
#define NE     8
#define HID    128
#define OUTD   16384
#define BMOFF  75497472
#define AUXOFF 150994944
#define CS_STR 131
#define BSTR   72          // padded bf16 stride for mma smem tiles

typedef unsigned long long ull;
typedef unsigned int u32;

// ---------------- device scratch ----------------
__device__ __align__(16) __nv_bfloat16 g_hh[2 * TOK * HID];
__device__ __align__(16) __nv_bfloat16 g_hl[2 * TOK * HID];
__device__ __align__(16) __nv_bfloat16 g_w2h[NE * OUTD * HID];
__device__ __align__(16) __nv_bfloat16 g_w2l[NE * OUTD * HID];
__device__ int   g_list[2][NE][TOK];
__device__ int   g_cnt[2][NE];
__device__ int   g_tiles[2][80];
__device__ float g_tokG[2 * TOK];
__device__ float g_psum[96][NE];
__device__ float g_lsum[96][NE];

__device__ __forceinline__ u32 s2u(const void* p) {
    u32 a; asm("{ .reg .u64 t; cvta.to.shared.u64 t, %1; cvt.u32.u64 %0, t; }" : "=r"(a) : "l"(p)); return a;
}
#define LDSM4(f, a) asm volatile("ldmatrix.sync.aligned.m8n8.x4.shared.b16 {%0,%1,%2,%3}, [%4];" \
    : "=r"((f)[0]), "=r"((f)[1]), "=r"((f)[2]), "=r"((f)[3]) : "r"(a))
#define LDSM2(f, a) asm volatile("ldmatrix.sync.aligned.m8n8.x2.shared.b16 {%0,%1}, [%2];" \
    : "=r"((f)[0]), "=r"((f)[1]) : "r"(a))
#define MMA(d, A, Bf) asm volatile( \
    "mma.sync.aligned.m16n8k16.row.col.f32.bf16.bf16.f32 {%0,%1,%2,%3},{%4,%5,%6,%7},{%8,%9},{%0,%1,%2,%3};" \
    : "+f"((d)[0]), "+f"((d)[1]), "+f"((d)[2]), "+f"((d)[3]) \
    : "r"((A)[0]), "r"((A)[1]), "r"((A)[2]), "r"((A)[3]), "r"((Bf)[0]), "r"((Bf)[1]))

__device__ __forceinline__ u32 hi2(float a, float b) {
    return (u32)__bfloat16_as_ushort(__float2bfloat16(a)) | ((u32)__bfloat16_as_ushort(__float2bfloat16(b)) << 16);
}
__device__ __forceinline__ u32 lo2(float a, float b) {
    float ra = a - __bfloat162float(__float2bfloat16(a));
    float rb = b - __bfloat162float(__float2bfloat16(b));
    return hi2(ra, rb);
}

// ---------------- K0 ----------------
__global__ void k_zero() { if (threadIdx.x < 16) ((int*)g_cnt)[threadIdx.x] = 0; }

// ---------------- K1: routing ----------------
__global__ void k_route(const float* __restrict__ z, const float* __restrict__ emb,
                        const float* __restrict__ Wr, const float* __restrict__ br) {
    int blk = blockIdx.x, b = blk / 3, s = blk - b * 3;
    int warp = threadIdx.x >> 5, lane = threadIdx.x & 31;
    float accP = 0.f, accL = 0.f;
    for (int it = 0; it < 24; it++) {
        int n = s * 96 + warp * 24 + it;
        int t = b * NTOT + n;
        float lg[8];
#pragma unroll
        for (int e = 0; e < 8; e++) lg[e] = 0.f;
        const float* zr = z + (size_t)t * LAT;
        const float* er = emb + (size_t)n * LAT;
        for (int i = lane; i < DIN; i += 32) {
            float xv = (i < LAT) ? zr[i] : er[i - LAT];
            const float4 w0 = *(const float4*)(Wr + i * 8);
            const float4 w1 = *(const float4*)(Wr + i * 8 + 4);
            lg[0] += xv * w0.x; lg[1] += xv * w0.y; lg[2] += xv * w0.z; lg[3] += xv * w0.w;
            lg[4] += xv * w1.x; lg[5] += xv * w1.y; lg[6] += xv * w1.z; lg[7] += xv * w1.w;
        }
#pragma unroll
        for (int off = 16; off > 0; off >>= 1)
#pragma unroll
            for (int e = 0; e < 8; e++) lg[e] += __shfl_xor_sync(0xffffffffu, lg[e], off);
#pragma unroll
        for (int e = 0; e < 8; e++) lg[e] = (lg[e] + br[e]) * (1.0f / 1.5f);
        int e0 = 0; float v0 = lg[0];
#pragma unroll
        for (int e = 1; e < 8; e++) if (lg[e] > v0) { v0 = lg[e]; e0 = e; }
        int e1 = -1; float v1 = -3.4e38f;
#pragma unroll
        for (int e = 0; e < 8; e++) if (e != e0 && lg[e] > v1) { v1 = lg[e]; e1 = e; }
        float ex = __expf(v1 - v0);
        float g0 = 1.f / (1.f + ex), g1 = ex * g0;
        float den = 0.f, pr[8];
#pragma unroll
        for (int e = 0; e < 8; e++) { pr[e] = __expf(lg[e] - v0); den += pr[e]; }
        float rden = 1.f / den;
        if (lane < 8) {
            accP += pr[lane] * rden;
            accL += (lane == e0 ? g0 : 0.f) + (lane == e1 ? g1 : 0.f);
        }
        if (lane == 0) {
            g_tokG[t] = g0; g_tokG[TOK + t] = g1;
            int p0 = atomicAdd(&g_cnt[0][e0], 1); g_list[0][e0][p0] = t;
            int p1 = atomicAdd(&g_cnt[1][e1], 1); g_list[1][e1][p1] = t;
        }
    }
    __shared__ float sP[4][8], sL[4][8];
    if (lane < 8) { sP[warp][lane] = accP; sL[warp][lane] = accL; }
    __syncthreads();
    if (threadIdx.x < 8) {
        float p = 0.f, l = 0.f;
        for (int w = 0; w < 4; w++) { p += sP[w][threadIdx.x]; l += sL[w][threadIdx.x]; }
        g_psum[blk][threadIdx.x] = p; g_lsum[blk][threadIdx.x] = l;
    }
}

// ---------------- K1b: tile schedule ----------------
__global__ void k_sched() {
    if (threadIdx.x == 0) {
        for (int s = 0; s < 2; s++) {
            int idx = 0;
            for (int e = 0; e < NE; e++) {
                int nt = (g_cnt[s][e] + 127) >> 7;
                for (int m = 0; m < nt; m++) g_tiles[s][idx++] = (e << 8) | m;
            }
            while (idx < 80) g_tiles[s][idx++] = -1;
        }
    }
}

// ---------------- K2: W2 -> permuted K-major bf16 hi/lo (128-col tiles) ----------------
__global__ void __launch_bounds__(128) k_w2t(const float* __restrict__ W2) {
    int nt = blockIdx.x, e = blockIdx.y;
    __shared__ float s[64][132];
    int tid = threadIdx.x;
    for (int kp = 0; kp < 2; kp++) {
        for (int task = tid; task < 1024; task += 128) {
            int k = task >> 4, r = task & 15;
            const float* src = W2 + ((size_t)(e * 128 + kp * 64 + k)) * OUTD + r * 1024 + nt * 8;
            float4 v0 = *(const float4*)src, v1 = *(const float4*)(src + 4);
            float* d = &s[k][r * 8];
            *(float4*)d = v0; *(float4*)(d + 4) = v1;
        }
        __syncthreads();
        int j = tid;
        size_t base = ((size_t)(e * OUTD + nt * 128 + j)) * HID + kp * 64;
#pragma unroll
        for (int c = 0; c < 8; c++) {
            u32 wh[4], wl[4];
#pragma unroll
            for (int p = 0; p < 4; p++) {
                float a = s[c * 8 + p * 2][j], b = s[c * 8 + p * 2 + 1][j];
                wh[p] = hi2(a, b); wl[p] = lo2(a, b);
            }
            *(uint4*)&g_w2h[base + c * 8] = make_uint4(wh[0], wh[1], wh[2], wh[3]);
            *(uint4*)&g_w2l[base + c * 8] = make_uint4(wl[0], wl[1], wl[2], wl[3]);
        }
        __syncthreads();
    }
}

// ---------------- K3: hidden GEMM + silu + gate -> bf16 hi/lo ----------------
__global__ void __launch_bounds__(256) k_hidden(const float* __restrict__ z,
                                                const float* __restrict__ emb,
                                                const float* __restrict__ W1,
                                                const float* __restrict__ b1) {
    int slot = blockIdx.z, e = blockIdx.y;
    int cnt = g_cnt[slot][e];
    int m0 = blockIdx.x * 64;
    if (m0 >= cnt) return;
    int rows = min(64, cnt - m0);
    __shared__ __align__(16) float Xs[16][64];
    __shared__ __align__(16) float Ws[16][128];
    __shared__ int stok[64];
    __shared__ float sg[64];
    int tid = threadIdx.x;
    if (tid < 64) {
        int t = (tid < rows) ? g_list[slot][e][m0 + tid] : -1;
        stok[tid] = t;
        sg[tid] = (t >= 0) ? g_tokG[slot * TOK + t] : 0.f;
    }
    __syncthreads();
    int tx = tid & 15, ty = tid >> 4, j0 = tx * 8, mr = ty * 4;
    float acc[4][8];
#pragma unroll
    for (int a = 0; a < 4; a++)
#pragma unroll
        for (int j = 0; j < 8; j++) acc[a][j] = 0.f;
    const float* W1e = W1 + (size_t)e * DIN * HID;
    int lm = tid >> 2, lq = (tid & 3) * 4, lk = tid >> 4, ln = (tid & 15) * 8;
    for (int k0 = 0; k0 < DIN; k0 += 16) {
        float4 v = make_float4(0.f, 0.f, 0.f, 0.f);
        int t = stok[lm];
        if (t >= 0) {
            int kk = k0 + lq;
            if (kk < LAT) v = *(const float4*)(z + (size_t)t * LAT + kk);
            else          v = *(const float4*)(emb + (size_t)(t % NTOT) * LAT + (kk - LAT));
        }
        const float* src = W1e + (size_t)(k0 + lk) * HID + ln;
        float4 w0 = *(const float4*)src, w1 = *(const float4*)(src + 4);
        __syncthreads();
        Xs[lq][lm] = v.x; Xs[lq + 1][lm] = v.y; Xs[lq + 2][lm] = v.z; Xs[lq + 3][lm] = v.w;
        *(float4*)&Ws[lk][ln] = w0; *(float4*)&Ws[lk][ln + 4] = w1;
        __syncthreads();
#pragma unroll
        for (int kk = 0; kk < 16; kk++) {
            float4 a = *(const float4*)&Xs[kk][mr];
            float4 b0 = *(const float4*)&Ws[kk][j0];
            float4 b1v = *(const float4*)&Ws[kk][j0 + 4];
            float av[4] = {a.x, a.y, a.z, a.w};
            float bv[8] = {b0.x, b0.y, b0.z, b0.w, b1v.x, b1v.y, b1v.z, b1v.w};
#pragma unroll
            for (int mm = 0; mm < 4; mm++)
#pragma unroll
                for (int jj = 0; jj < 8; jj++)
                    acc[mm][jj] = fmaf(av[mm], bv[jj], acc[mm][jj]);
        }
    }
    const float* b1e = b1 + e * HID;
#pragma unroll
    for (int mm = 0; mm < 4; mm++) {
        int m = mr + mm, t = stok[m];
        if (t < 0) continue;
        float g = sg[m], o[8];
#pragma unroll
        for (int jj = 0; jj < 8; jj++) {
            float c = acc[mm][jj] + b1e[j0 + jj];
            o[jj] = c * g / (1.f + __expf(-c));
        }
        size_t base = ((size_t)(slot * TOK + t)) * HID + j0;
        *(uint4*)&g_hh[base] = make_uint4(hi2(o[0], o[1]), hi2(o[2], o[3]), hi2(o[4], o[5]), hi2(o[6], o[7]));
        *(uint4*)&g_hl[base] = make_uint4(lo2(o[0], o[1]), lo2(o[2], o[3]), lo2(o[4], o[5]), lo2(o[6], o[7]));
    }
}

// ---------------- K4: output GEMM via mma.sync bf16, M=128 x N=128, K=128, 3-term split
// smem layout (bf16, stride BSTR=72): Ah | Al | Bh | Bl, each 128*72*2 = 18432 B
__global__ void __launch_bounds__(256) k_out_mma(const float* __restrict__ b2,
                                                 float* __restrict__ out, int slot) {
    int ti = g_tiles[slot][blockIdx.x];
    if (ti < 0) return;
    int e = (ti >> 8) & 7, m0 = (ti & 255) * 128;
    int rows = min(128, g_cnt[slot][e] - m0);
    int nt = blockIdx.y, h0 = nt * 8;

    extern __shared__ __align__(16) __nv_bfloat16 sm[];
    u32 smb = s2u(sm);
    __nv_bfloat16* sAh = sm;
    __nv_bfloat16* sAl = sm + 128 * BSTR;
    __nv_bfloat16* sBh = sm + 2 * 128 * BSTR;
    __nv_bfloat16* sBl = sm + 3 * 128 * BSTR;
    __shared__ int   sbase[128];
    __shared__ float sg[128];

    int tid = threadIdx.x, wid = tid >> 5, lane = tid & 31;
    int wm = wid >> 2, wn = wid & 3;

    int tA = -1;
    if (tid < 128) {
        int base = -1; float g = 0.f;
        if (tid < rows) {
            tA = g_list[slot][e][m0 + tid];
            g = g_tokG[slot * TOK + tA];
            int b = tA / NTOT, n = tA - b * NTOT;
            int s = n / 96, rem = n - s * 96, l = rem >> 2, jt = rem & 3;
            int chunk = ((b * 3 + s) * 24 + l) * 2 + (jt >> 1);
            base = chunk * OUTD + (jt & 1);
        }
        sbase[tid] = base; sg[tid] = g;
    }
    __syncthreads();
    int tAr = (tid >> 1) < rows ? g_list[slot][e][m0 + (tid >> 1)] : -1;   // A-load row token

    float acc[4][4][4];
#pragma unroll
    for (int i = 0; i < 4; i++)
#pragma unroll
        for (int j = 0; j < 4; j++)
#pragma unroll
            for (int p = 0; p < 4; p++) acc[i][j][p] = 0.f;

    // ldmatrix base addresses (bytes)
    u32 aRow = wm * 64 + (lane & 7) + ((lane >> 3) & 1) * 8;
    u32 aKof = (lane >> 4) * 8;
    int ll = lane & 15;
    u32 bRow = wn * 32 + (ll & 7);
    u32 bKof = ((ll >> 3) & 1) * 8;
    u32 aAddrH = smb + (aRow * BSTR + aKof) * 2;
    u32 aAddrL = aAddrH + 128 * BSTR * 2;
    u32 bAddrH = smb + 2 * 128 * BSTR * 2 + (bRow * BSTR + bKof) * 2;
    u32 bAddrL = bAddrH + 128 * BSTR * 2;

    int lr = tid >> 1, half = tid & 1;   // load mapping: 2 threads/row, 32 bf16 each
    for (int kc = 0; kc < 2; kc++) {
        // load A (hi/lo) and B (hi/lo) chunk kc
        {
            const uint4* ah = (tAr >= 0) ? (const uint4*)(g_hh + ((size_t)(slot * TOK + tAr)) * HID + kc * 64 + half * 32) : (const uint4*)0;
            const uint4* al = (tAr >= 0) ? (const uint4*)(g_hl + ((size_t)(slot * TOK + tAr)) * HID + kc * 64 + half * 32) : (const uint4*)0;
            uint4 z4 = make_uint4(0, 0, 0, 0);
            uint4* dh = (uint4*)(sAh + lr * BSTR + half * 32);
            uint4* dl = (uint4*)(sAl + lr * BSTR + half * 32);
#pragma unroll
            for (int q = 0; q < 4; q++) {
                dh[q] = (tAr >= 0) ? ah[q] : z4;
                dl[q] = (tAr >= 0) ? al[q] : z4;
            }
            const uint4* bh = (const uint4*)(g_w2h + ((size_t)(e * OUTD + nt * 128 + lr)) * HID + kc * 64 + half * 32);
            const uint4* bl = (const uint4*)(g_w2l + ((size_t)(e * OUTD + nt * 128 + lr)) * HID + kc * 64 + half * 32);
            uint4* eh = (uint4*)(sBh + lr * BSTR + half * 32);
            uint4* el = (uint4*)(sBl + lr * BSTR + half * 32);
#pragma unroll
            for (int q = 0; q < 4; q++) { eh[q] = bh[q]; el[q] = bl[q]; }
        }
        __syncthreads();
#pragma unroll
        for (int ks = 0; ks < 4; ks++) {
            u32 koff = (ks * 16) * 2;
            u32 af[4][4], bhf[4][2], blf[4][2];
#pragma unroll
            for (int mt = 0; mt < 4; mt++) LDSM4(af[mt], aAddrH + mt * 16 * BSTR * 2 + koff);
#pragma unroll
            for (int nn = 0; nn < 4; nn++) {
                LDSM2(bhf[nn], bAddrH + nn * 8 * BSTR * 2 + koff);
                LDSM2(blf[nn], bAddrL + nn * 8 * BSTR * 2 + koff);
            }
#pragma unroll
            for (int mt = 0; mt < 4; mt++)
#pragma unroll
                for (int nn = 0; nn < 4; nn++) {
                    MMA(acc[mt][nn], af[mt], bhf[nn]);
                    MMA(acc[mt][nn], af[mt], blf[nn]);
                }
#pragma unroll
            for (int mt = 0; mt < 4; mt++) LDSM4(af[mt], aAddrL + mt * 16 * BSTR * 2 + koff);
#pragma unroll
            for (int mt = 0; mt < 4; mt++)
#pragma unroll
                for (int nn = 0; nn < 4; nn++)
                    MMA(acc[mt][nn], af[mt], bhf[nn]);
        }
        __syncthreads();
    }

    // acc -> Cs [col][m], stride CS_STR
    float* Cs = (float*)sm;
#pragma unroll
    for (int mt = 0; mt < 4; mt++)
#pragma unroll
        for (int nn = 0; nn < 4; nn++) {
            int row = wm * 64 + mt * 16 + (lane >> 2);
            int col = wn * 32 + nn * 8 + (lane & 3) * 2;
            Cs[col * CS_STR + row]           = acc[mt][nn][0];
            Cs[(col + 1) * CS_STR + row]     = acc[mt][nn][1];
            Cs[col * CS_STR + row + 8]       = acc[mt][nn][2];
            Cs[(col + 1) * CS_STR + row + 8] = acc[mt][nn][3];
        }
    __syncthreads();

    const float* b2e = b2 + e * OUTD;
    int tc = tid & 127, mh = tid >> 7;
    float bA = b2e[(tc >> 3) * 1024 + h0 + (tc & 7)];
    float bB = b2e[(tc & 15) * 1024 + h0 + (tc >> 4)];
    int jB = (tc & 15) * 8 + (tc >> 4);
    int aoffA = (tc >> 3) * 1024 + h0 + (tc & 7);
    int aoffB = h0 * 16 + tc;

#pragma unroll 4
    for (int mi = 0; mi < 64; mi++) {
        int m = mi * 2 + mh;
        int bs = sbase[m];
        if (bs < 0) continue;
        float g = sg[m];
        size_t addr; float v;
        if (bs & 1) {
            v = Cs[jB * CS_STR + m] + g * bB;
            addr = (size_t)BMOFF + (size_t)(bs & ~1) + aoffB;
        } else {
            v = Cs[tc * CS_STR + m] + g * bA;
            addr = (size_t)bs + aoffA;
        }
        if (slot == 0) out[addr] = v;
        else           out[addr] += v;
    }
}

// ---------------- K5: aux ----------------
__global__ void k_aux(float* __restrict__ out) {
    if (threadIdx.x == 0 && blockIdx.x == 0) {
        double aux = 0.0;
        for (int s = 0; s < 3; s++) {
            double dot = 0.0;
            for (int e = 0; e < NE; e++) {
                double P = 0.0, L = 0.0;
                for (int b = 0; b < 32; b++) {
                    P += (double)g_psum[b * 3 + s][e];
                    L += (double)g_lsum[b * 3 + s][e];
                }
                dot += P * L;
            }
            double a = 8.0 * dot / (3072.0 * 3072.0) - 1.0;
            if (a > 0.0) aux += a;
        }
        out[AUXOFF] = (float)aux;
    }
}

extern "C" void kernel_launch(void* const* d_in, const int* in_sizes, int n_in,
                              void* d_out, int out_size) {
    const float* z   = (const float*)d_in[0];
    const float* emb = (const float*)d_in[1];
    const float* Wr  = (const float*)d_in[2];
    const float* br  = (const float*)d_in[3];
    const float* W1  = (const float*)d_in[4];
    const float* b1  = (const float*)d_in[5];
    const float* W2  = (const float*)d_in[6];
    const float* b2  = (const float*)d_in[7];
    float* out = (float*)d_out;
    (void)in_sizes; (void)n_in; (void)out_size;

    int smem = 4 * 128 * BSTR * 2;   // 73728 B
    cudaFuncSetAttribute(k_out_mma, cudaFuncAttributeMaxDynamicSharedMemorySize, smem);

    k_zero<<<1, 32>>>();
    k_route<<<96, 128>>>(z, emb, Wr, br);
    k_sched<<<1, 32>>>();
    k_w2t<<<dim3(128, NE), 128>>>(W2);
    k_hidden<<<dim3(TOK / 64, NE, 2), 256>>>(z, emb, W1, b1);
    k_out_mma<<<dim3(80, 128), 256, smem>>>(b2, out, 0);
    k_out_mma<<<dim3(80, 128), 256, smem>>>(b2, out, 1);
    k_aux<<<1, 32>>>(out);
}

// round 10
// speedup vs baseline: 1.9547x; 1.3207x over previous
#include <cuda_runtime.h>
#include <cuda_bf16.h>

#define TOK    9216
#define NTOT   288
#define LAT    256
#define DIN    512
#define NE     8
#define HID    128
#define OUTD   16384
#define BMOFF  75497472
#define AUXOFF 150994944
#define CS_STR 131
#define BSTR   72          // padded bf16 stride for mma smem tiles

typedef unsigned long long ull;
typedef unsigned int u32;

// ---------------- device scratch ----------------
__device__ __align__(16) __nv_bfloat16 g_hh[2 * TOK * HID];
__device__ __align__(16) __nv_bfloat16 g_hl[2 * TOK * HID];
__device__ __align__(16) __nv_bfloat16 g_w2h[NE * OUTD * HID];
__device__ __align__(16) __nv_bfloat16 g_w2l[NE * OUTD * HID];
__device__ int   g_list[2][NE][TOK];
__device__ int   g_cnt[2][NE];
__device__ int   g_tiles[2][80];
__device__ float g_tokG[2 * TOK];
__device__ float g_psum[96][NE];
__device__ float g_lsum[96][NE];

__device__ __forceinline__ u32 s2u(const void* p) {
    u32 a; asm("{ .reg .u64 t; cvta.to.shared.u64 t, %1; cvt.u32.u64 %0, t; }" : "=r"(a) : "l"(p)); return a;
}
#define LDSM4(f, a) asm volatile("ldmatrix.sync.aligned.m8n8.x4.shared.b16 {%0,%1,%2,%3}, [%4];" \
    : "=r"((f)[0]), "=r"((f)[1]), "=r"((f)[2]), "=r"((f)[3]) : "r"(a))
#define LDSM2(f, a) asm volatile("ldmatrix.sync.aligned.m8n8.x2.shared.b16 {%0,%1}, [%2];" \
    : "=r"((f)[0]), "=r"((f)[1]) : "r"(a))
#define MMA(d, A, Bf) asm volatile( \
    "mma.sync.aligned.m16n8k16.row.col.f32.bf16.bf16.f32 {%0,%1,%2,%3},{%4,%5,%6,%7},{%8,%9},{%0,%1,%2,%3};" \
    : "+f"((d)[0]), "+f"((d)[1]), "+f"((d)[2]), "+f"((d)[3]) \
    : "r"((A)[0]), "r"((A)[1]), "r"((A)[2]), "r"((A)[3]), "r"((Bf)[0]), "r"((Bf)[1]))

__device__ __forceinline__ u32 hi2(float a, float b) {
    return (u32)__bfloat16_as_ushort(__float2bfloat16(a)) | ((u32)__bfloat16_as_ushort(__float2bfloat16(b)) << 16);
}
__device__ __forceinline__ u32 lo2(float a, float b) {
    float ra = a - __bfloat162float(__float2bfloat16(a));
    float rb = b - __bfloat162float(__float2bfloat16(b));
    return hi2(ra, rb);
}

// ---------------- K0 ----------------
__global__ void k_zero() { if (threadIdx.x < 16) ((int*)g_cnt)[threadIdx.x] = 0; }

// ---------------- K1: routing ----------------
__global__ void k_route(const float* __restrict__ z, const float* __restrict__ emb,
                        const float* __restrict__ Wr, const float* __restrict__ br) {
    int blk = blockIdx.x, b = blk / 3, s = blk - b * 3;
    int warp = threadIdx.x >> 5, lane = threadIdx.x & 31;
    float accP = 0.f, accL = 0.f;
    for (int it = 0; it < 24; it++) {
        int n = s * 96 + warp * 24 + it;
        int t = b * NTOT + n;
        float lg[8];
#pragma unroll
        for (int e = 0; e < 8; e++) lg[e] = 0.f;
        const float* zr = z + (size_t)t * LAT;
        const float* er = emb + (size_t)n * LAT;
        for (int i = lane; i < DIN; i += 32) {
            float xv = (i < LAT) ? zr[i] : er[i - LAT];
            const float4 w0 = *(const float4*)(Wr + i * 8);
            const float4 w1 = *(const float4*)(Wr + i * 8 + 4);
            lg[0] += xv * w0.x; lg[1] += xv * w0.y; lg[2] += xv * w0.z; lg[3] += xv * w0.w;
            lg[4] += xv * w1.x; lg[5] += xv * w1.y; lg[6] += xv * w1.z; lg[7] += xv * w1.w;
        }
#pragma unroll
        for (int off = 16; off > 0; off >>= 1)
#pragma unroll
            for (int e = 0; e < 8; e++) lg[e] += __shfl_xor_sync(0xffffffffu, lg[e], off);
#pragma unroll
        for (int e = 0; e < 8; e++) lg[e] = (lg[e] + br[e]) * (1.0f / 1.5f);
        int e0 = 0; float v0 = lg[0];
#pragma unroll
        for (int e = 1; e < 8; e++) if (lg[e] > v0) { v0 = lg[e]; e0 = e; }
        int e1 = -1; float v1 = -3.4e38f;
#pragma unroll
        for (int e = 0; e < 8; e++) if (e != e0 && lg[e] > v1) { v1 = lg[e]; e1 = e; }
        float ex = __expf(v1 - v0);
        float g0 = 1.f / (1.f + ex), g1 = ex * g0;
        float den = 0.f, pr[8];
#pragma unroll
        for (int e = 0; e < 8; e++) { pr[e] = __expf(lg[e] - v0); den += pr[e]; }
        float rden = 1.f / den;
        if (lane < 8) {
            accP += pr[lane] * rden;
            accL += (lane == e0 ? g0 : 0.f) + (lane == e1 ? g1 : 0.f);
        }
        if (lane == 0) {
            g_tokG[t] = g0; g_tokG[TOK + t] = g1;
            int p0 = atomicAdd(&g_cnt[0][e0], 1); g_list[0][e0][p0] = t;
            int p1 = atomicAdd(&g_cnt[1][e1], 1); g_list[1][e1][p1] = t;
        }
    }
    __shared__ float sP[4][8], sL[4][8];
    if (lane < 8) { sP[warp][lane] = accP; sL[warp][lane] = accL; }
    __syncthreads();
    if (threadIdx.x < 8) {
        float p = 0.f, l = 0.f;
        for (int w = 0; w < 4; w++) { p += sP[w][threadIdx.x]; l += sL[w][threadIdx.x]; }
        g_psum[blk][threadIdx.x] = p; g_lsum[blk][threadIdx.x] = l;
    }
}

// ---------------- K1b: tile schedule ----------------
__global__ void k_sched() {
    if (threadIdx.x == 0) {
        for (int s = 0; s < 2; s++) {
            int idx = 0;
            for (int e = 0; e < NE; e++) {
                int nt = (g_cnt[s][e] + 127) >> 7;
                for (int m = 0; m < nt; m++) g_tiles[s][idx++] = (e << 8) | m;
            }
            while (idx < 80) g_tiles[s][idx++] = -1;
        }
    }
}

// ---------------- K2: W2 -> permuted K-major bf16 hi/lo (128-col tiles) ----------------
__global__ void __launch_bounds__(128) k_w2t(const float* __restrict__ W2) {
    int nt = blockIdx.x, e = blockIdx.y;
    __shared__ float s[64][132];
    int tid = threadIdx.x;
    for (int kp = 0; kp < 2; kp++) {
        for (int task = tid; task < 1024; task += 128) {
            int k = task >> 4, r = task & 15;
            const float* src = W2 + ((size_t)(e * 128 + kp * 64 + k)) * OUTD + r * 1024 + nt * 8;
            float4 v0 = *(const float4*)src, v1 = *(const float4*)(src + 4);
            float* d = &s[k][r * 8];
            *(float4*)d = v0; *(float4*)(d + 4) = v1;
        }
        __syncthreads();
        int j = tid;
        size_t base = ((size_t)(e * OUTD + nt * 128 + j)) * HID + kp * 64;
#pragma unroll
        for (int c = 0; c < 8; c++) {
            u32 wh[4], wl[4];
#pragma unroll
            for (int p = 0; p < 4; p++) {
                float a = s[c * 8 + p * 2][j], b = s[c * 8 + p * 2 + 1][j];
                wh[p] = hi2(a, b); wl[p] = lo2(a, b);
            }
            *(uint4*)&g_w2h[base + c * 8] = make_uint4(wh[0], wh[1], wh[2], wh[3]);
            *(uint4*)&g_w2l[base + c * 8] = make_uint4(wl[0], wl[1], wl[2], wl[3]);
        }
        __syncthreads();
    }
}

// ---------------- K3: hidden GEMM + silu + gate -> bf16 hi/lo ----------------
__global__ void __launch_bounds__(256) k_hidden(const float* __restrict__ z,
                                                const float* __restrict__ emb,
                                                const float* __restrict__ W1,
                                                const float* __restrict__ b1) {
    int slot = blockIdx.z, e = blockIdx.y;
    int cnt = g_cnt[slot][e];
    int m0 = blockIdx.x * 64;
    if (m0 >= cnt) return;
    int rows = min(64, cnt - m0);
    __shared__ __align__(16) float Xs[16][64];
    __shared__ __align__(16) float Ws[16][128];
    __shared__ int stok[64];
    __shared__ float sg[64];
    int tid = threadIdx.x;
    if (tid < 64) {
        int t = (tid < rows) ? g_list[slot][e][m0 + tid] : -1;
        stok[tid] = t;
        sg[tid] = (t >= 0) ? g_tokG[slot * TOK + t] : 0.f;
    }
    __syncthreads();
    int tx = tid & 15, ty = tid >> 4, j0 = tx * 8, mr = ty * 4;
    float acc[4][8];
#pragma unroll
    for (int a = 0; a < 4; a++)
#pragma unroll
        for (int j = 0; j < 8; j++) acc[a][j] = 0.f;
    const float* W1e = W1 + (size_t)e * DIN * HID;
    int lm = tid >> 2, lq = (tid & 3) * 4, lk = tid >> 4, ln = (tid & 15) * 8;
    for (int k0 = 0; k0 < DIN; k0 += 16) {
        float4 v = make_float4(0.f, 0.f, 0.f, 0.f);
        int t = stok[lm];
        if (t >= 0) {
            int kk = k0 + lq;
            if (kk < LAT) v = *(const float4*)(z + (size_t)t * LAT + kk);
            else          v = *(const float4*)(emb + (size_t)(t % NTOT) * LAT + (kk - LAT));
        }
        const float* src = W1e + (size_t)(k0 + lk) * HID + ln;
        float4 w0 = *(const float4*)src, w1 = *(const float4*)(src + 4);
        __syncthreads();
        Xs[lq][lm] = v.x; Xs[lq + 1][lm] = v.y; Xs[lq + 2][lm] = v.z; Xs[lq + 3][lm] = v.w;
        *(float4*)&Ws[lk][ln] = w0; *(float4*)&Ws[lk][ln + 4] = w1;
        __syncthreads();
#pragma unroll
        for (int kk = 0; kk < 16; kk++) {
            float4 a = *(const float4*)&Xs[kk][mr];
            float4 b0 = *(const float4*)&Ws[kk][j0];
            float4 b1v = *(const float4*)&Ws[kk][j0 + 4];
            float av[4] = {a.x, a.y, a.z, a.w};
            float bv[8] = {b0.x, b0.y, b0.z, b0.w, b1v.x, b1v.y, b1v.z, b1v.w};
#pragma unroll
            for (int mm = 0; mm < 4; mm++)
#pragma unroll
                for (int jj = 0; jj < 8; jj++)
                    acc[mm][jj] = fmaf(av[mm], bv[jj], acc[mm][jj]);
        }
    }
    const float* b1e = b1 + e * HID;
#pragma unroll
    for (int mm = 0; mm < 4; mm++) {
        int m = mr + mm, t = stok[m];
        if (t < 0) continue;
        float g = sg[m], o[8];
#pragma unroll
        for (int jj = 0; jj < 8; jj++) {
            float c = acc[mm][jj] + b1e[j0 + jj];
            o[jj] = c * g / (1.f + __expf(-c));
        }
        size_t base = ((size_t)(slot * TOK + t)) * HID + j0;
        *(uint4*)&g_hh[base] = make_uint4(hi2(o[0], o[1]), hi2(o[2], o[3]), hi2(o[4], o[5]), hi2(o[6], o[7]));
        *(uint4*)&g_hl[base] = make_uint4(lo2(o[0], o[1]), lo2(o[2], o[3]), lo2(o[4], o[5]), lo2(o[6], o[7]));
    }
}

// ---------------- K4: output GEMM via mma.sync bf16, M=128 x N=128, K=128, 3-term split
// smem layout (bf16, stride BSTR=72): Ah | Al | Bh | Bl, each 128*72*2 = 18432 B
__global__ void __launch_bounds__(256, 2) k_out_mma(const float* __restrict__ b2,
                                                    float* __restrict__ out, int slot) {
    int ti = g_tiles[slot][blockIdx.x];
    if (ti < 0) return;
    int e = (ti >> 8) & 7, m0 = (ti & 255) * 128;
    int rows = min(128, g_cnt[slot][e] - m0);
    int nt = blockIdx.y, h0 = nt * 8;

    extern __shared__ __align__(16) __nv_bfloat16 sm[];
    u32 smb = s2u(sm);
    __nv_bfloat16* sAh = sm;
    __nv_bfloat16* sAl = sm + 128 * BSTR;
    __nv_bfloat16* sBh = sm + 2 * 128 * BSTR;
    __nv_bfloat16* sBl = sm + 3 * 128 * BSTR;
    __shared__ int   sbase[128];
    __shared__ float sg[128];

    int tid = threadIdx.x, wid = tid >> 5, lane = tid & 31;
    int wm = wid >> 2, wn = wid & 3;

    if (tid < 128) {
        int base = -1; float g = 0.f;
        if (tid < rows) {
            int tA = g_list[slot][e][m0 + tid];
            g = g_tokG[slot * TOK + tA];
            int b = tA / NTOT, n = tA - b * NTOT;
            int s = n / 96, rem = n - s * 96, l = rem >> 2, jt = rem & 3;
            int chunk = ((b * 3 + s) * 24 + l) * 2 + (jt >> 1);
            base = chunk * OUTD + (jt & 1);
        }
        sbase[tid] = base; sg[tid] = g;
    }
    __syncthreads();
    int tAr = (tid >> 1) < rows ? g_list[slot][e][m0 + (tid >> 1)] : -1;   // A-load row token

    float acc[4][4][4];
#pragma unroll
    for (int i = 0; i < 4; i++)
#pragma unroll
        for (int j = 0; j < 4; j++)
#pragma unroll
            for (int p = 0; p < 4; p++) acc[i][j][p] = 0.f;

    // ldmatrix base addresses (bytes)
    u32 aRow = wm * 64 + (lane & 7) + ((lane >> 3) & 1) * 8;
    u32 aKof = (lane >> 4) * 8;
    int ll = lane & 15;
    u32 bRow = wn * 32 + (ll & 7);
    u32 bKof = ((ll >> 3) & 1) * 8;
    u32 aAddrH = smb + (aRow * BSTR + aKof) * 2;
    u32 aAddrL = aAddrH + 128 * BSTR * 2;
    u32 bAddrH = smb + 2 * 128 * BSTR * 2 + (bRow * BSTR + bKof) * 2;
    u32 bAddrL = bAddrH + 128 * BSTR * 2;

    int lr = tid >> 1, half = tid & 1;   // load mapping: 2 threads/row, 32 bf16 each
    for (int kc = 0; kc < 2; kc++) {
        {
            const uint4* ah = (tAr >= 0) ? (const uint4*)(g_hh + ((size_t)(slot * TOK + tAr)) * HID + kc * 64 + half * 32) : (const uint4*)0;
            const uint4* al = (tAr >= 0) ? (const uint4*)(g_hl + ((size_t)(slot * TOK + tAr)) * HID + kc * 64 + half * 32) : (const uint4*)0;
            uint4 z4 = make_uint4(0, 0, 0, 0);
            uint4* dh = (uint4*)(sAh + lr * BSTR + half * 32);
            uint4* dl = (uint4*)(sAl + lr * BSTR + half * 32);
#pragma unroll
            for (int q = 0; q < 4; q++) {
                dh[q] = (tAr >= 0) ? ah[q] : z4;
                dl[q] = (tAr >= 0) ? al[q] : z4;
            }
            const uint4* bh = (const uint4*)(g_w2h + ((size_t)(e * OUTD + nt * 128 + lr)) * HID + kc * 64 + half * 32);
            const uint4* bl = (const uint4*)(g_w2l + ((size_t)(e * OUTD + nt * 128 + lr)) * HID + kc * 64 + half * 32);
            uint4* eh = (uint4*)(sBh + lr * BSTR + half * 32);
            uint4* el = (uint4*)(sBl + lr * BSTR + half * 32);
#pragma unroll
            for (int q = 0; q < 4; q++) { eh[q] = bh[q]; el[q] = bl[q]; }
        }
        __syncthreads();
#pragma unroll
        for (int ks = 0; ks < 4; ks++) {
            u32 koff = (ks * 16) * 2;
            u32 af[4][4], bhf[4][2], blf[4][2];
#pragma unroll
            for (int mt = 0; mt < 4; mt++) LDSM4(af[mt], aAddrH + mt * 16 * BSTR * 2 + koff);
#pragma unroll
            for (int nn = 0; nn < 4; nn++) {
                LDSM2(bhf[nn], bAddrH + nn * 8 * BSTR * 2 + koff);
                LDSM2(blf[nn], bAddrL + nn * 8 * BSTR * 2 + koff);
            }
#pragma unroll
            for (int mt = 0; mt < 4; mt++)
#pragma unroll
                for (int nn = 0; nn < 4; nn++) {
                    MMA(acc[mt][nn], af[mt], bhf[nn]);
                    MMA(acc[mt][nn], af[mt], blf[nn]);
                }
#pragma unroll
            for (int mt = 0; mt < 4; mt++) LDSM4(af[mt], aAddrL + mt * 16 * BSTR * 2 + koff);
#pragma unroll
            for (int mt = 0; mt < 4; mt++)
#pragma unroll
                for (int nn = 0; nn < 4; nn++)
                    MMA(acc[mt][nn], af[mt], bhf[nn]);
        }
        __syncthreads();
    }

    // acc -> Cs [col][m], stride CS_STR
    float* Cs = (float*)sm;
#pragma unroll
    for (int mt = 0; mt < 4; mt++)
#pragma unroll
        for (int nn = 0; nn < 4; nn++) {
            int row = wm * 64 + mt * 16 + (lane >> 2);
            int col = wn * 32 + nn * 8 + (lane & 3) * 2;
            Cs[col * CS_STR + row]           = acc[mt][nn][0];
            Cs[(col + 1) * CS_STR + row]     = acc[mt][nn][1];
            Cs[col * CS_STR + row + 8]       = acc[mt][nn][2];
            Cs[(col + 1) * CS_STR + row + 8] = acc[mt][nn][3];
        }
    __syncthreads();

    // vectorized epilogue: 8 rows/iter, 32 threads/row, float4 stores
    const float* b2e = b2 + e * OUTD;
    int q = tid & 31, rowgrp = tid >> 5;
    // A-row mapping: col j = rA*8 + h4A + u  ->  o = rA*1024 + h0 + h4A + u
    int rA = q >> 1, h4A = (q & 1) * 4;
    int aoffA = rA * 1024 + h0 + h4A;
    int jA = rA * 8 + h4A;
    float biasA[4];
#pragma unroll
    for (int u = 0; u < 4; u++) biasA[u] = b2e[aoffA + u];
    // Bm-row mapping: addr off = h0*16 + q*4 + u, (h-h0) = q>>2, r = (q&3)*4+u
    int hB = q >> 2, rB4 = (q & 3) * 4;
    int aoffB = h0 * 16 + q * 4;
    int jB[4]; float biasB[4];
#pragma unroll
    for (int u = 0; u < 4; u++) {
        jB[u] = (rB4 + u) * 8 + hB;
        biasB[u] = b2e[(rB4 + u) * 1024 + h0 + hB];
    }

#pragma unroll 2
    for (int it = 0; it < 16; it++) {
        int m = it * 8 + rowgrp;
        int bs = sbase[m];
        if (bs < 0) continue;
        float g = sg[m];
        float4 v; size_t addr;
        if (bs & 1) {
            v.x = Cs[jB[0] * CS_STR + m] + g * biasB[0];
            v.y = Cs[jB[1] * CS_STR + m] + g * biasB[1];
            v.z = Cs[jB[2] * CS_STR + m] + g * biasB[2];
            v.w = Cs[jB[3] * CS_STR + m] + g * biasB[3];
            addr = (size_t)BMOFF + (size_t)(bs & ~1) + aoffB;
        } else {
            v.x = Cs[(jA + 0) * CS_STR + m] + g * biasA[0];
            v.y = Cs[(jA + 1) * CS_STR + m] + g * biasA[1];
            v.z = Cs[(jA + 2) * CS_STR + m] + g * biasA[2];
            v.w = Cs[(jA + 3) * CS_STR + m] + g * biasA[3];
            addr = (size_t)bs + aoffA;
        }
        if (slot == 0) {
            *(float4*)(out + addr) = v;
        } else {
            float4 o = *(const float4*)(out + addr);
            v.x += o.x; v.y += o.y; v.z += o.z; v.w += o.w;
            *(float4*)(out + addr) = v;
        }
    }
}

// ---------------- K5: aux ----------------
__global__ void k_aux(float* __restrict__ out) {
    if (threadIdx.x == 0 && blockIdx.x == 0) {
        double aux = 0.0;
        for (int s = 0; s < 3; s++) {
            double dot = 0.0;
            for (int e = 0; e < NE; e++) {
                double P = 0.0, L = 0.0;
                for (int b = 0; b < 32; b++) {
                    P += (double)g_psum[b * 3 + s][e];
                    L += (double)g_lsum[b * 3 + s][e];
                }
                dot += P * L;
            }
            double a = 8.0 * dot / (3072.0 * 3072.0) - 1.0;
            if (a > 0.0) aux += a;
        }
        out[AUXOFF] = (float)aux;
    }
}

extern "C" void kernel_launch(void* const* d_in, const int* in_sizes, int n_in,
                              void* d_out, int out_size) {
    const float* z   = (const float*)d_in[0];
    const float* emb = (const float*)d_in[1];
    const float* Wr  = (const float*)d_in[2];
    const float* br  = (const float*)d_in[3];
    const float* W1  = (const float*)d_in[4];
    const float* b1  = (const float*)d_in[5];
    const float* W2  = (const float*)d_in[6];
    const float* b2  = (const float*)d_in[7];
    float* out = (float*)d_out;
    (void)in_sizes; (void)n_in; (void)out_size;

    int smem = 4 * 128 * BSTR * 2;   // 73728 B
    cudaFuncSetAttribute(k_out_mma, cudaFuncAttributeMaxDynamicSharedMemorySize, smem);

    k_zero<<<1, 32>>>();
    k_route<<<96, 128>>>(z, emb, Wr, br);
    k_sched<<<1, 32>>>();
    k_w2t<<<dim3(128, NE), 128>>>(W2);
    k_hidden<<<dim3(TOK / 64, NE, 2), 256>>>(z, emb, W1, b1);
    k_out_mma<<<dim3(80, 128), 256, smem>>>(b2, out, 0);
    k_out_mma<<<dim3(80, 128), 256, smem>>>(b2, out, 1);
    k_aux<<<1, 32>>>(out);
}

// round 11
// speedup vs baseline: 2.4529x; 1.2549x over previous
#include <cuda_runtime.h>
#include <cuda_bf16.h>

#define TOK    9216
#define NTOT   288
#define LAT    256
#define DIN    512
#define NE     8
#define HID    128
#define OUTD   16384
#define BMOFF  75497472
#define AUXOFF 150994944
#define CS_STR 131
#define BSTR   72
#define MAXT   104

typedef unsigned long long ull;
typedef unsigned int u32;

// ---------------- device scratch ----------------
__device__ __align__(16) __nv_bfloat16 g_hh[2 * TOK * HID];
__device__ __align__(16) __nv_bfloat16 g_hl[2 * TOK * HID];
__device__ __align__(16) __nv_bfloat16 g_w2h[NE * OUTD * HID];
__device__ __align__(16) __nv_bfloat16 g_w2l[NE * OUTD * HID];
__device__ int   g_list[2][NE][TOK];
__device__ int   g_cnt[2][NE];
__device__ int   g_plist[64][TOK];    // token | (sa<<14), bucketed by pair a*8+b
__device__ int   g_pcnt[64];
__device__ int   g_tiles[MAXT];
__device__ float g_tokG[2 * TOK];
__device__ float g_psum[96][NE];
__device__ float g_lsum[96][NE];

__device__ __forceinline__ u32 s2u(const void* p) {
    u32 a; asm("{ .reg .u64 t; cvta.to.shared.u64 t, %1; cvt.u32.u64 %0, t; }" : "=r"(a) : "l"(p)); return a;
}
#define LDSM4(f, a) asm volatile("ldmatrix.sync.aligned.m8n8.x4.shared.b16 {%0,%1,%2,%3}, [%4];" \
    : "=r"((f)[0]), "=r"((f)[1]), "=r"((f)[2]), "=r"((f)[3]) : "r"(a))
#define LDSM2(f, a) asm volatile("ldmatrix.sync.aligned.m8n8.x2.shared.b16 {%0,%1}, [%2];" \
    : "=r"((f)[0]), "=r"((f)[1]) : "r"(a))
#define MMA(d, A, Bf) asm volatile( \
    "mma.sync.aligned.m16n8k16.row.col.f32.bf16.bf16.f32 {%0,%1,%2,%3},{%4,%5,%6,%7},{%8,%9},{%0,%1,%2,%3};" \
    : "+f"((d)[0]), "+f"((d)[1]), "+f"((d)[2]), "+f"((d)[3]) \
    : "r"((A)[0]), "r"((A)[1]), "r"((A)[2]), "r"((A)[3]), "r"((Bf)[0]), "r"((Bf)[1]))

__device__ __forceinline__ u32 hi2(float a, float b) {
    return (u32)__bfloat16_as_ushort(__float2bfloat16(a)) | ((u32)__bfloat16_as_ushort(__float2bfloat16(b)) << 16);
}
__device__ __forceinline__ u32 lo2(float a, float b) {
    float ra = a - __bfloat162float(__float2bfloat16(a));
    float rb = b - __bfloat162float(__float2bfloat16(b));
    return hi2(ra, rb);
}

// ---------------- K0 ----------------
__global__ void k_zero() {
    int i = threadIdx.x;
    if (i < 16) ((int*)g_cnt)[i] = 0;
    if (i < 64) g_pcnt[i] = 0;
}

// ---------------- K1: routing (512 thr: 16 warps x 6 tokens) ----------------
__global__ void __launch_bounds__(512) k_route(const float* __restrict__ z, const float* __restrict__ emb,
                                               const float* __restrict__ Wr, const float* __restrict__ br) {
    int blk = blockIdx.x, b = blk / 3, s = blk - b * 3;
    int warp = threadIdx.x >> 5, lane = threadIdx.x & 31;
    float accP = 0.f, accL = 0.f;
    for (int it = 0; it < 6; it++) {
        int n = s * 96 + warp * 6 + it;
        int t = b * NTOT + n;
        float lg[8];
#pragma unroll
        for (int e = 0; e < 8; e++) lg[e] = 0.f;
        const float* zr = z + (size_t)t * LAT;
        const float* er = emb + (size_t)n * LAT;
        for (int i = lane; i < DIN; i += 32) {
            float xv = (i < LAT) ? zr[i] : er[i - LAT];
            const float4 w0 = *(const float4*)(Wr + i * 8);
            const float4 w1 = *(const float4*)(Wr + i * 8 + 4);
            lg[0] += xv * w0.x; lg[1] += xv * w0.y; lg[2] += xv * w0.z; lg[3] += xv * w0.w;
            lg[4] += xv * w1.x; lg[5] += xv * w1.y; lg[6] += xv * w1.z; lg[7] += xv * w1.w;
        }
#pragma unroll
        for (int off = 16; off > 0; off >>= 1)
#pragma unroll
            for (int e = 0; e < 8; e++) lg[e] += __shfl_xor_sync(0xffffffffu, lg[e], off);
#pragma unroll
        for (int e = 0; e < 8; e++) lg[e] = (lg[e] + br[e]) * (1.0f / 1.5f);
        int e0 = 0; float v0 = lg[0];
#pragma unroll
        for (int e = 1; e < 8; e++) if (lg[e] > v0) { v0 = lg[e]; e0 = e; }
        int e1 = -1; float v1 = -3.4e38f;
#pragma unroll
        for (int e = 0; e < 8; e++) if (e != e0 && lg[e] > v1) { v1 = lg[e]; e1 = e; }
        float ex = __expf(v1 - v0);
        float g0 = 1.f / (1.f + ex), g1 = ex * g0;
        float den = 0.f, pr[8];
#pragma unroll
        for (int e = 0; e < 8; e++) { pr[e] = __expf(lg[e] - v0); den += pr[e]; }
        float rden = 1.f / den;
        if (lane < 8) {
            accP += pr[lane] * rden;
            accL += (lane == e0 ? g0 : 0.f) + (lane == e1 ? g1 : 0.f);
        }
        if (lane == 0) {
            g_tokG[t] = g0; g_tokG[TOK + t] = g1;
            int p0 = atomicAdd(&g_cnt[0][e0], 1); g_list[0][e0][p0] = t;
            int p1 = atomicAdd(&g_cnt[1][e1], 1); g_list[1][e1][p1] = t;
            int a = min(e0, e1), bb = max(e0, e1);
            int sa = (e0 < e1) ? 0 : 1;                 // slot holding expert a
            int pp = a * 8 + bb;
            int pos = atomicAdd(&g_pcnt[pp], 1);
            g_plist[pp][pos] = t | (sa << 14);
        }
    }
    __shared__ float sP[16][8], sL[16][8];
    if (lane < 8) { sP[warp][lane] = accP; sL[warp][lane] = accL; }
    __syncthreads();
    if (threadIdx.x < 8) {
        float p = 0.f, l = 0.f;
        for (int w = 0; w < 16; w++) { p += sP[w][threadIdx.x]; l += sL[w][threadIdx.x]; }
        g_psum[blk][threadIdx.x] = p; g_lsum[blk][threadIdx.x] = l;
    }
}

// ---------------- K1b: pair tile schedule ----------------
__global__ void k_sched() {
    if (threadIdx.x == 0) {
        int idx = 0;
        for (int p = 0; p < 64; p++) {
            int c = g_pcnt[p];
            int nt = (c + 127) >> 7;
            for (int m = 0; m < nt && idx < MAXT; m++) g_tiles[idx++] = (p << 8) | m;
        }
        while (idx < MAXT) g_tiles[idx++] = -1;
    }
}

// ---------------- K2: W2 -> permuted K-major bf16 hi/lo ----------------
__global__ void __launch_bounds__(128) k_w2t(const float* __restrict__ W2) {
    int nt = blockIdx.x, e = blockIdx.y;
    __shared__ float s[64][132];
    int tid = threadIdx.x;
    for (int kp = 0; kp < 2; kp++) {
        for (int task = tid; task < 1024; task += 128) {
            int k = task >> 4, r = task & 15;
            const float* src = W2 + ((size_t)(e * 128 + kp * 64 + k)) * OUTD + r * 1024 + nt * 8;
            float4 v0 = *(const float4*)src, v1 = *(const float4*)(src + 4);
            float* d = &s[k][r * 8];
            *(float4*)d = v0; *(float4*)(d + 4) = v1;
        }
        __syncthreads();
        int j = tid;
        size_t base = ((size_t)(e * OUTD + nt * 128 + j)) * HID + kp * 64;
#pragma unroll
        for (int c = 0; c < 8; c++) {
            u32 wh[4], wl[4];
#pragma unroll
            for (int p = 0; p < 4; p++) {
                float a = s[c * 8 + p * 2][j], b = s[c * 8 + p * 2 + 1][j];
                wh[p] = hi2(a, b); wl[p] = lo2(a, b);
            }
            *(uint4*)&g_w2h[base + c * 8] = make_uint4(wh[0], wh[1], wh[2], wh[3]);
            *(uint4*)&g_w2l[base + c * 8] = make_uint4(wl[0], wl[1], wl[2], wl[3]);
        }
        __syncthreads();
    }
}

// ---------------- K3: hidden GEMM + silu + gate -> bf16 hi/lo ----------------
__global__ void __launch_bounds__(256) k_hidden(const float* __restrict__ z,
                                                const float* __restrict__ emb,
                                                const float* __restrict__ W1,
                                                const float* __restrict__ b1) {
    int slot = blockIdx.z, e = blockIdx.y;
    int cnt = g_cnt[slot][e];
    int m0 = blockIdx.x * 64;
    if (m0 >= cnt) return;
    int rows = min(64, cnt - m0);
    __shared__ __align__(16) float Xs[16][64];
    __shared__ __align__(16) float Ws[16][128];
    __shared__ int stok[64];
    __shared__ float sg[64];
    int tid = threadIdx.x;
    if (tid < 64) {
        int t = (tid < rows) ? g_list[slot][e][m0 + tid] : -1;
        stok[tid] = t;
        sg[tid] = (t >= 0) ? g_tokG[slot * TOK + t] : 0.f;
    }
    __syncthreads();
    int tx = tid & 15, ty = tid >> 4, j0 = tx * 8, mr = ty * 4;
    float acc[4][8];
#pragma unroll
    for (int a = 0; a < 4; a++)
#pragma unroll
        for (int j = 0; j < 8; j++) acc[a][j] = 0.f;
    const float* W1e = W1 + (size_t)e * DIN * HID;
    int lm = tid >> 2, lq = (tid & 3) * 4, lk = tid >> 4, ln = (tid & 15) * 8;
    for (int k0 = 0; k0 < DIN; k0 += 16) {
        float4 v = make_float4(0.f, 0.f, 0.f, 0.f);
        int t = stok[lm];
        if (t >= 0) {
            int kk = k0 + lq;
            if (kk < LAT) v = *(const float4*)(z + (size_t)t * LAT + kk);
            else          v = *(const float4*)(emb + (size_t)(t % NTOT) * LAT + (kk - LAT));
        }
        const float* src = W1e + (size_t)(k0 + lk) * HID + ln;
        float4 w0 = *(const float4*)src, w1 = *(const float4*)(src + 4);
        __syncthreads();
        Xs[lq][lm] = v.x; Xs[lq + 1][lm] = v.y; Xs[lq + 2][lm] = v.z; Xs[lq + 3][lm] = v.w;
        *(float4*)&Ws[lk][ln] = w0; *(float4*)&Ws[lk][ln + 4] = w1;
        __syncthreads();
#pragma unroll
        for (int kk = 0; kk < 16; kk++) {
            float4 a = *(const float4*)&Xs[kk][mr];
            float4 b0 = *(const float4*)&Ws[kk][j0];
            float4 b1v = *(const float4*)&Ws[kk][j0 + 4];
            float av[4] = {a.x, a.y, a.z, a.w};
            float bv[8] = {b0.x, b0.y, b0.z, b0.w, b1v.x, b1v.y, b1v.z, b1v.w};
#pragma unroll
            for (int mm = 0; mm < 4; mm++)
#pragma unroll
                for (int jj = 0; jj < 8; jj++)
                    acc[mm][jj] = fmaf(av[mm], bv[jj], acc[mm][jj]);
        }
    }
    const float* b1e = b1 + e * HID;
#pragma unroll
    for (int mm = 0; mm < 4; mm++) {
        int m = mr + mm, t = stok[m];
        if (t < 0) continue;
        float g = sg[m], o[8];
#pragma unroll
        for (int jj = 0; jj < 8; jj++) {
            float c = acc[mm][jj] + b1e[j0 + jj];
            o[jj] = c * g / (1.f + __expf(-c));
        }
        size_t base = ((size_t)(slot * TOK + t)) * HID + j0;
        *(uint4*)&g_hh[base] = make_uint4(hi2(o[0], o[1]), hi2(o[2], o[3]), hi2(o[4], o[5]), hi2(o[6], o[7]));
        *(uint4*)&g_hl[base] = make_uint4(lo2(o[0], o[1]), lo2(o[2], o[3]), lo2(o[4], o[5]), lo2(o[6], o[7]));
    }
}

// ---------------- K4: pair-fused output GEMM. M=128 x N=128, K=2x128, single write.
__global__ void __launch_bounds__(256, 2) k_out_pair(const float* __restrict__ b2,
                                                     float* __restrict__ out) {
    int ti = g_tiles[blockIdx.x];
    if (ti < 0) return;
    int pp = ti >> 8, ea = pp >> 3, eb = pp & 7;
    int m0 = (ti & 255) * 128;
    int rows = min(128, g_pcnt[pp] - m0);
    int nt = blockIdx.y, h0 = nt * 8;

    extern __shared__ __align__(16) __nv_bfloat16 sm[];
    u32 smb = s2u(sm);
    __nv_bfloat16* sAh = sm;
    __nv_bfloat16* sAl = sm + 128 * BSTR;
    __nv_bfloat16* sBh = sm + 2 * 128 * BSTR;
    __nv_bfloat16* sBl = sm + 3 * 128 * BSTR;
    __shared__ int   sbase[128];
    __shared__ int   srcrow[128];    // slot*TOK + t for expert a
    __shared__ float sga[128], sgb[128];

    int tid = threadIdx.x, wid = tid >> 5, lane = tid & 31;
    int wm = wid >> 2, wn = wid & 3;

    if (tid < 128) {
        int base = -1, sr = 0; float ga = 0.f, gb = 0.f;
        if (tid < rows) {
            int tt = g_plist[pp][m0 + tid];
            int t = tt & 16383, sa = (tt >> 14) & 1;
            ga = g_tokG[sa * TOK + t];
            gb = g_tokG[(1 - sa) * TOK + t];
            sr = sa * TOK + t;
            int b = t / NTOT, n = t - b * NTOT;
            int s = n / 96, rem = n - s * 96, l = rem >> 2, jt = rem & 3;
            int chunk = ((b * 3 + s) * 24 + l) * 2 + (jt >> 1);
            base = chunk * OUTD + (jt & 1);
        }
        sbase[tid] = base; srcrow[tid] = sr; sga[tid] = ga; sgb[tid] = gb;
    }
    __syncthreads();

    float acc[4][4][4];
#pragma unroll
    for (int i = 0; i < 4; i++)
#pragma unroll
        for (int j = 0; j < 4; j++)
#pragma unroll
            for (int p = 0; p < 4; p++) acc[i][j][p] = 0.f;

    u32 aRow = wm * 64 + (lane & 7) + ((lane >> 3) & 1) * 8;
    u32 aKof = (lane >> 4) * 8;
    int ll = lane & 15;
    u32 bRow = wn * 32 + (ll & 7);
    u32 bKof = ((ll >> 3) & 1) * 8;
    u32 aAddrH = smb + (aRow * BSTR + aKof) * 2;
    u32 aAddrL = aAddrH + 128 * BSTR * 2;
    u32 bAddrH = smb + 2 * 128 * BSTR * 2 + (bRow * BSTR + bKof) * 2;
    u32 bAddrL = bAddrH + 128 * BSTR * 2;

    int lr = tid >> 1, half = tid & 1;
    bool valid = lr < rows;
    int sra = valid ? srcrow[lr] : 0;

    for (int ch = 0; ch < 4; ch++) {          // {expert a, expert b} x {kc0, kc1}
        int ph = ch >> 1, kc = ch & 1;
        int e = ph ? eb : ea;
        // A source row: expert a -> slot sa; expert b -> other slot (flip by TOK)
        int rowidx = sra;
        if (ph) rowidx = (sra >= TOK) ? (sra - TOK) : (sra + TOK);
        {
            size_t aoff = ((size_t)rowidx) * HID + kc * 64 + half * 32;
            const uint4* ah = (const uint4*)(g_hh + aoff);
            const uint4* al = (const uint4*)(g_hl + aoff);
            uint4 z4 = make_uint4(0, 0, 0, 0);
            uint4* dh = (uint4*)(sAh + lr * BSTR + half * 32);
            uint4* dl = (uint4*)(sAl + lr * BSTR + half * 32);
#pragma unroll
            for (int q = 0; q < 4; q++) {
                dh[q] = valid ? ah[q] : z4;
                dl[q] = valid ? al[q] : z4;
            }
            size_t boff = ((size_t)(e * OUTD + nt * 128 + lr)) * HID + kc * 64 + half * 32;
            const uint4* bh = (const uint4*)(g_w2h + boff);
            const uint4* bl = (const uint4*)(g_w2l + boff);
            uint4* eh = (uint4*)(sBh + lr * BSTR + half * 32);
            uint4* el = (uint4*)(sBl + lr * BSTR + half * 32);
#pragma unroll
            for (int q = 0; q < 4; q++) { eh[q] = bh[q]; el[q] = bl[q]; }
        }
        __syncthreads();
#pragma unroll
        for (int ks = 0; ks < 4; ks++) {
            u32 koff = (ks * 16) * 2;
            u32 af[4][4], bhf[4][2], blf[4][2];
#pragma unroll
            for (int mt = 0; mt < 4; mt++) LDSM4(af[mt], aAddrH + mt * 16 * BSTR * 2 + koff);
#pragma unroll
            for (int nn = 0; nn < 4; nn++) {
                LDSM2(bhf[nn], bAddrH + nn * 8 * BSTR * 2 + koff);
                LDSM2(blf[nn], bAddrL + nn * 8 * BSTR * 2 + koff);
            }
#pragma unroll
            for (int mt = 0; mt < 4; mt++)
#pragma unroll
                for (int nn = 0; nn < 4; nn++) {
                    MMA(acc[mt][nn], af[mt], bhf[nn]);
                    MMA(acc[mt][nn], af[mt], blf[nn]);
                }
#pragma unroll
            for (int mt = 0; mt < 4; mt++) LDSM4(af[mt], aAddrL + mt * 16 * BSTR * 2 + koff);
#pragma unroll
            for (int mt = 0; mt < 4; mt++)
#pragma unroll
                for (int nn = 0; nn < 4; nn++)
                    MMA(acc[mt][nn], af[mt], bhf[nn]);
        }
        __syncthreads();
    }

    // acc -> Cs [col][m]
    float* Cs = (float*)sm;
#pragma unroll
    for (int mt = 0; mt < 4; mt++)
#pragma unroll
        for (int nn = 0; nn < 4; nn++) {
            int row = wm * 64 + mt * 16 + (lane >> 2);
            int col = wn * 32 + nn * 8 + (lane & 3) * 2;
            Cs[col * CS_STR + row]           = acc[mt][nn][0];
            Cs[(col + 1) * CS_STR + row]     = acc[mt][nn][1];
            Cs[col * CS_STR + row + 8]       = acc[mt][nn][2];
            Cs[(col + 1) * CS_STR + row + 8] = acc[mt][nn][3];
        }
    __syncthreads();

    // vectorized single-write epilogue
    const float* ba = b2 + ea * OUTD;
    const float* bb = b2 + eb * OUTD;
    int q = tid & 31, rowgrp = tid >> 5;
    int rA = q >> 1, h4A = (q & 1) * 4;
    int aoffA = rA * 1024 + h0 + h4A;
    int jA = rA * 8 + h4A;
    float bAa[4], bAb[4];
#pragma unroll
    for (int u = 0; u < 4; u++) { bAa[u] = ba[aoffA + u]; bAb[u] = bb[aoffA + u]; }
    int hB = q >> 2, rB4 = (q & 3) * 4;
    int aoffB = h0 * 16 + q * 4;
    int jB[4]; float bBa[4], bBb[4];
#pragma unroll
    for (int u = 0; u < 4; u++) {
        jB[u] = (rB4 + u) * 8 + hB;
        bBa[u] = ba[(rB4 + u) * 1024 + h0 + hB];
        bBb[u] = bb[(rB4 + u) * 1024 + h0 + hB];
    }

#pragma unroll 2
    for (int it = 0; it < 16; it++) {
        int m = it * 8 + rowgrp;
        int bs = sbase[m];
        if (bs < 0) continue;
        float ga = sga[m], gb = sgb[m];
        float4 v; size_t addr;
        if (bs & 1) {
            v.x = Cs[jB[0] * CS_STR + m] + ga * bBa[0] + gb * bBb[0];
            v.y = Cs[jB[1] * CS_STR + m] + ga * bBa[1] + gb * bBb[1];
            v.z = Cs[jB[2] * CS_STR + m] + ga * bBa[2] + gb * bBb[2];
            v.w = Cs[jB[3] * CS_STR + m] + ga * bBa[3] + gb * bBb[3];
            addr = (size_t)BMOFF + (size_t)(bs & ~1) + aoffB;
        } else {
            v.x = Cs[(jA + 0) * CS_STR + m] + ga * bAa[0] + gb * bAb[0];
            v.y = Cs[(jA + 1) * CS_STR + m] + ga * bAa[1] + gb * bAb[1];
            v.z = Cs[(jA + 2) * CS_STR + m] + ga * bAa[2] + gb * bAb[2];
            v.w = Cs[(jA + 3) * CS_STR + m] + ga * bAa[3] + gb * bAb[3];
            addr = (size_t)bs + aoffA;
        }
        *(float4*)(out + addr) = v;
    }
}

// ---------------- K5: aux ----------------
__global__ void k_aux(float* __restrict__ out) {
    if (threadIdx.x == 0 && blockIdx.x == 0) {
        double aux = 0.0;
        for (int s = 0; s < 3; s++) {
            double dot = 0.0;
            for (int e = 0; e < NE; e++) {
                double P = 0.0, L = 0.0;
                for (int b = 0; b < 32; b++) {
                    P += (double)g_psum[b * 3 + s][e];
                    L += (double)g_lsum[b * 3 + s][e];
                }
                dot += P * L;
            }
            double a = 8.0 * dot / (3072.0 * 3072.0) - 1.0;
            if (a > 0.0) aux += a;
        }
        out[AUXOFF] = (float)aux;
    }
}

extern "C" void kernel_launch(void* const* d_in, const int* in_sizes, int n_in,
                              void* d_out, int out_size) {
    const float* z   = (const float*)d_in[0];
    const float* emb = (const float*)d_in[1];
    const float* Wr  = (const float*)d_in[2];
    const float* br  = (const float*)d_in[3];
    const float* W1  = (const float*)d_in[4];
    const float* b1  = (const float*)d_in[5];
    const float* W2  = (const float*)d_in[6];
    const float* b2  = (const float*)d_in[7];
    float* out = (float*)d_out;
    (void)in_sizes; (void)n_in; (void)out_size;

    int smem = 4 * 128 * BSTR * 2;   // 73728 B
    cudaFuncSetAttribute(k_out_pair, cudaFuncAttributeMaxDynamicSharedMemorySize, smem);

    k_zero<<<1, 64>>>();
    k_route<<<96, 512>>>(z, emb, Wr, br);
    k_sched<<<1, 32>>>();
    k_w2t<<<dim3(128, NE), 128>>>(W2);
    k_hidden<<<dim3(TOK / 64, NE, 2), 256>>>(z, emb, W1, b1);
    k_out_pair<<<dim3(MAXT, 128), 256, smem>>>(b2, out);
    k_aux<<<1, 32>>>(out);
}